// round 4
// baseline (speedup 1.0000x reference)
#include <cuda_runtime.h>
#include <cuda_bf16.h>

// Problem constants: B=64, S=512, H=1024, L=9
#define BB 64
#define SS 512
#define HH 1024
#define LL 9
#define ROWS_PER_BLOCK 32
#define MAIN_BLOCK 256          // 8 warps; warp = 4 rows x 8 K-slices

// Scratch (no cudaMalloc allowed)
__device__ int g_gather[BB * SS];
__device__ int g_nvalid[BB];
__device__ int g_flat_in[BB * SS];    // b*512 + src  (gathered source row)
__device__ int g_flat_out[BB * SS];   // b*512 + j    (compacted destination row)
__device__ int g_total;

// ---------------------------------------------------------------------------
// Kernel A: per-batch stable compaction (prefix scan over valid_mask)
// ---------------------------------------------------------------------------
__global__ __launch_bounds__(SS) void ner_scan_kernel(const int* __restrict__ mask)
{
    int b = blockIdx.x;
    int t = threadIdx.x;
    int m = mask[b * SS + t];

    int lane = t & 31;
    int w    = t >> 5;

    int v = m;
    #pragma unroll
    for (int o = 1; o < 32; o <<= 1) {
        int n = __shfl_up_sync(0xFFFFFFFFu, v, o);
        if (lane >= o) v += n;
    }

    __shared__ int wsum[16];
    if (lane == 31) wsum[w] = v;
    __syncthreads();

    if (t < 16) {
        int s = wsum[t];
        #pragma unroll
        for (int o = 1; o < 16; o <<= 1) {
            int n = __shfl_up_sync(0x0000FFFFu, s, o);
            if (t >= o) s += n;
        }
        wsum[t] = s;
    }
    __syncthreads();

    int incl = v + (w ? wsum[w - 1] : 0);
    if (m) g_gather[b * SS + incl - 1] = t;      // stable compaction
    if (t == SS - 1) g_nvalid[b] = incl;
}

// ---------------------------------------------------------------------------
// Kernel A3: build flat valid-row list + write softmax(bias) to invalid rows.
// 64 blocks x 512 threads. Each block redundantly scans the 64 nv counts.
// ---------------------------------------------------------------------------
__global__ __launch_bounds__(SS) void ner_flatten_kernel(
    const float* __restrict__ bias, float* __restrict__ out)
{
    __shared__ int snv[64], sincl[64];
    int b = blockIdx.x;
    int t = threadIdx.x;

    if (t < 64) snv[t] = g_nvalid[t];
    __syncthreads();
    if (t < 64) {
        int v = snv[t];
        int lane = t & 31;
        #pragma unroll
        for (int o = 1; o < 32; o <<= 1) {
            int n = __shfl_up_sync(0xFFFFFFFFu, v, o);
            if (lane >= o) v += n;
        }
        sincl[t] = v;
    }
    __syncthreads();
    if (t >= 32 && t < 64) sincl[t] += sincl[31];
    __syncthreads();

    int nv   = snv[b];
    int base = sincl[b] - nv;

    if (b == 0 && t == 0) g_total = sincl[63];

    if (t < nv) {
        g_flat_in[base + t]  = b * SS + g_gather[b * SS + t];
        g_flat_out[base + t] = b * SS + t;
    } else {
        // invalid (padded) destination row: softmax(bias)
        float logit[LL];
        #pragma unroll
        for (int l = 0; l < LL; l++) logit[l] = bias[l];
        float m = logit[0];
        #pragma unroll
        for (int l = 1; l < LL; l++) m = fmaxf(m, logit[l]);
        float e[LL], s = 0.f;
        #pragma unroll
        for (int l = 0; l < LL; l++) { e[l] = __expf(logit[l] - m); s += e[l]; }
        float inv = 1.0f / s;
        float* __restrict__ o = out + ((size_t)b * SS + (size_t)t) * LL;
        #pragma unroll
        for (int l = 0; l < LL; l++) o[l] = e[l] * inv;
    }
}

// ---------------------------------------------------------------------------
// Kernel B: valid rows only. Warp = 4 rows (rp = lane>>3) x 8 K-slices
// (c = lane&7, interleaved at 16B granularity) -> each LDG.128 warp-inst
// covers 128B contiguous per row (4 wavefronts). W from SMEM as LDS.128,
// one 128B-spanning broadcast phase per (label, iter). Packed f32x2 FMA.
// ---------------------------------------------------------------------------
__global__ __launch_bounds__(MAIN_BLOCK) void ner_main_kernel(
    const float* __restrict__ seq,
    const float* __restrict__ W,
    const float* __restrict__ bias,
    float* __restrict__ out)
{
    int total = g_total;
    if ((int)blockIdx.x * ROWS_PER_BLOCK >= total) return;   // tail block: no work

    // Wsh (as u64 pairs): Wsh[l*512 + p] = (W[2p][l], W[2p+1][l])
    __shared__ unsigned long long Wsh[LL * 512];   // 36,864 B

    int tid = threadIdx.x;
    for (int i = tid; i < LL * 512; i += MAIN_BLOCK) {
        int l = i >> 9;          // / 512
        int p = i & 511;
        float lo = W[(2 * p) * LL + l];
        float hi = W[(2 * p + 1) * LL + l];
        unsigned long long u;
        asm("mov.b64 %0, {%1, %2};" : "=l"(u) : "f"(lo), "f"(hi));
        Wsh[i] = u;
    }
    __syncthreads();

    int lane = tid & 31;
    int c    = lane & 7;         // K-slice 0..7 (fast dim -> coalesced LDG)
    int rp   = lane >> 3;        // row slot 0..3 within warp
    int warp = tid >> 5;

    int r = blockIdx.x * ROWS_PER_BLOCK + warp * 4 + rp;
    bool live = (r < total);
    int rc = live ? r : 0;                 // clamp; garbage discarded
    int in_idx  = g_flat_in[rc];
    int out_idx = g_flat_out[rc];

    // x as ulonglong2 units (4 floats = 2 pairs): unit j = it*8 + c, it=0..31
    const ulonglong2* __restrict__ xr =
        (const ulonglong2*)seq + (size_t)in_idx * (HH / 4);
    const ulonglong2* __restrict__ Wp2 = (const ulonglong2*)Wsh;

    unsigned long long acc[LL];
    #pragma unroll
    for (int l = 0; l < LL; l++) acc[l] = 0ull;

    for (int it0 = 0; it0 < 32; it0 += 4) {
        // batch 4 independent 16B loads (front-batched -> MLP)
        ulonglong2 x0 = xr[(it0 + 0) * 8 + c];
        ulonglong2 x1 = xr[(it0 + 1) * 8 + c];
        ulonglong2 x2 = xr[(it0 + 2) * 8 + c];
        ulonglong2 x3 = xr[(it0 + 3) * 8 + c];

        #pragma unroll
        for (int l = 0; l < LL; l++) {
            int wb = l * 256;   // ulonglong2 units per label
            ulonglong2 w0 = Wp2[wb + (it0 + 0) * 8 + c];
            asm("fma.rn.f32x2 %0, %1, %2, %0;" : "+l"(acc[l]) : "l"(x0.x), "l"(w0.x));
            asm("fma.rn.f32x2 %0, %1, %2, %0;" : "+l"(acc[l]) : "l"(x0.y), "l"(w0.y));
            ulonglong2 w1 = Wp2[wb + (it0 + 1) * 8 + c];
            asm("fma.rn.f32x2 %0, %1, %2, %0;" : "+l"(acc[l]) : "l"(x1.x), "l"(w1.x));
            asm("fma.rn.f32x2 %0, %1, %2, %0;" : "+l"(acc[l]) : "l"(x1.y), "l"(w1.y));
            ulonglong2 w2 = Wp2[wb + (it0 + 2) * 8 + c];
            asm("fma.rn.f32x2 %0, %1, %2, %0;" : "+l"(acc[l]) : "l"(x2.x), "l"(w2.x));
            asm("fma.rn.f32x2 %0, %1, %2, %0;" : "+l"(acc[l]) : "l"(x2.y), "l"(w2.y));
            ulonglong2 w3 = Wp2[wb + (it0 + 3) * 8 + c];
            asm("fma.rn.f32x2 %0, %1, %2, %0;" : "+l"(acc[l]) : "l"(x3.x), "l"(w3.x));
            asm("fma.rn.f32x2 %0, %1, %2, %0;" : "+l"(acc[l]) : "l"(x3.y), "l"(w3.y));
        }
    }

    // unpack + reduce across the 8 K-slices (xor 1,2,4 within each rp group)
    float sum[LL];
    #pragma unroll
    for (int l = 0; l < LL; l++) {
        float lo, hi;
        asm("mov.b64 {%0, %1}, %2;" : "=f"(lo), "=f"(hi) : "l"(acc[l]));
        sum[l] = lo + hi;
        sum[l] += __shfl_xor_sync(0xFFFFFFFFu, sum[l], 1);
        sum[l] += __shfl_xor_sync(0xFFFFFFFFu, sum[l], 2);
        sum[l] += __shfl_xor_sync(0xFFFFFFFFu, sum[l], 4);
    }

    if (c == 0 && live) {
        float logit[LL];
        #pragma unroll
        for (int l = 0; l < LL; l++) logit[l] = sum[l] + bias[l];
        float m = logit[0];
        #pragma unroll
        for (int l = 1; l < LL; l++) m = fmaxf(m, logit[l]);
        float e[LL], s = 0.f;
        #pragma unroll
        for (int l = 0; l < LL; l++) { e[l] = __expf(logit[l] - m); s += e[l]; }
        float inv = 1.0f / s;
        float* __restrict__ o = out + (size_t)out_idx * LL;
        #pragma unroll
        for (int l = 0; l < LL; l++) o[l] = e[l] * inv;
    }
}

// ---------------------------------------------------------------------------
// Launch. Inputs: [0] seq f32 [64,512,1024], [1] mask i32 [64,512],
//                 [2] W f32 [1024,9], [3] b f32 [9]; out f32 [64,512,9]
// ---------------------------------------------------------------------------
extern "C" void kernel_launch(void* const* d_in, const int* in_sizes, int n_in,
                              void* d_out, int out_size)
{
    const float* seq  = (const float*)d_in[0];
    const int*   mask = (const int*)  d_in[1];
    const float* W    = (const float*)d_in[2];
    const float* bias = (const float*)d_in[3];
    float*       out  = (float*)d_out;

    ner_scan_kernel<<<BB, SS>>>(mask);
    ner_flatten_kernel<<<BB, SS>>>(bias, out);

    // covers worst case: all 32768 rows valid
    ner_main_kernel<<<(BB * SS) / ROWS_PER_BLOCK, MAIN_BLOCK>>>(seq, W, bias, out);
}

// round 6
// speedup vs baseline: 1.2164x; 1.2164x over previous
#include <cuda_runtime.h>
#include <cuda_bf16.h>

// Problem constants: B=64, S=512, H=1024, L=9
#define BB 64
#define SS 512
#define HH 1024
#define LL 9
#define MAIN_BLOCK 256      // 8 warps; warp = 4 slot-pairs x 8 K-slices, 2 rows/slot

// Scratch (no cudaMalloc allowed)
__device__ int g_gather[BB * SS];
__device__ int g_nvalid[BB];
__device__ unsigned long long g_Wpk[LL * 512];   // packed: [l*512+q] = (W[2q][l], W[2q+1][l])

// ---------------------------------------------------------------------------
// Kernel A: per-batch stable compaction scan  +  one-time W f32x2 packing
// ---------------------------------------------------------------------------
__global__ __launch_bounds__(SS) void ner_prep_kernel(
    const int* __restrict__ mask, const float* __restrict__ W)
{
    int b = blockIdx.x;
    int t = threadIdx.x;

    // --- one-time W pack (blocks 0..8 cover the 4608 entries) ---
    if (b < LL) {
        int idx = b * SS + t;
        int l = idx >> 9;
        int q = idx & 511;
        float lo = W[(2 * q) * LL + l];
        float hi = W[(2 * q + 1) * LL + l];
        unsigned long long u;
        asm("mov.b64 %0, {%1, %2};" : "=l"(u) : "f"(lo), "f"(hi));
        g_Wpk[idx] = u;
    }

    // --- stable compaction scan over valid_mask[b,:] ---
    int m = mask[b * SS + t];
    int lane = t & 31;
    int w    = t >> 5;

    int v = m;
    #pragma unroll
    for (int o = 1; o < 32; o <<= 1) {
        int n = __shfl_up_sync(0xFFFFFFFFu, v, o);
        if (lane >= o) v += n;
    }

    __shared__ int wsum[16];
    if (lane == 31) wsum[w] = v;
    __syncthreads();

    if (t < 16) {
        int s = wsum[t];
        #pragma unroll
        for (int o = 1; o < 16; o <<= 1) {
            int n = __shfl_up_sync(0x0000FFFFu, s, o);
            if (t >= o) s += n;
        }
        wsum[t] = s;
    }
    __syncthreads();

    int incl = v + (w ? wsum[w - 1] : 0);
    if (m) g_gather[b * SS + incl - 1] = t;      // stable compaction
    if (t == SS - 1) g_nvalid[b] = incl;
}

// ---------------------------------------------------------------------------
// Kernel B: block = one token slot j for ALL 64 batches. Warp = 4 slot-pairs
// (rp = lane>>3, rows bA=2*(w*4+rp), bB=bA+1) x 8 K-slices (c = lane&7,
// 16B-interleaved -> each LDG.128 warp-inst covers 128B contiguous x 4 rows
// = 4 wavefronts). W staged coalesced from pre-packed global; each W pair is
// read from SMEM once and reused for 2 rows. Packed f32x2 FMA. Invalid rows
// emit softmax(bias) through the same epilogue.
// ---------------------------------------------------------------------------
__global__ __launch_bounds__(MAIN_BLOCK) void ner_main_kernel(
    const float* __restrict__ seq,
    const float* __restrict__ bias,
    float* __restrict__ out)
{
    __shared__ unsigned long long Wsh[LL * 512];   // 36,864 B

    int j    = blockIdx.x;          // token slot 0..511 (same for whole block)
    int tid  = threadIdx.x;
    int lane = tid & 31;
    int c    = lane & 7;            // K-slice (fast dim -> coalesced LDG)
    int rp   = lane >> 3;           // slot-pair within warp
    int w    = tid >> 5;

    int bA = (w * 4 + rp) * 2;      // 0,2,...,62
    int bB = bA + 1;

    bool validA = (j < g_nvalid[bA]);
    bool validB = (j < g_nvalid[bB]);

    // Tail blocks (no valid rows at this j): skip the 37 KB W staging
    int has = __syncthreads_or((int)(validA || validB));
    if (has) {
        ulonglong2* __restrict__ Ws2 = (ulonglong2*)Wsh;
        const ulonglong2* __restrict__ Wg2 = (const ulonglong2*)g_Wpk;
        for (int i = tid; i < LL * 256; i += MAIN_BLOCK) Ws2[i] = Wg2[i];  // coalesced 16B
        __syncthreads();
    }

    unsigned long long accA[LL], accB[LL];
    #pragma unroll
    for (int l = 0; l < LL; l++) { accA[l] = 0ull; accB[l] = 0ull; }

    if (__any_sync(0xFFFFFFFFu, validA || validB)) {
        int srcA = validA ? g_gather[bA * SS + j] : 0;
        int srcB = validB ? g_gather[bB * SS + j] : 0;
        const ulonglong2* __restrict__ xrA =
            (const ulonglong2*)seq + (size_t)(bA * SS + srcA) * (HH / 4);
        const ulonglong2* __restrict__ xrB =
            (const ulonglong2*)seq + (size_t)(bB * SS + srcB) * (HH / 4);
        const ulonglong2* __restrict__ Wp2 = (const ulonglong2*)Wsh;

        for (int it0 = 0; it0 < 32; it0 += 4) {
            // batch 8 independent predicated 16B loads (MLP=8 per thread)
            ulonglong2 xA[4], xB[4];
            #pragma unroll
            for (int u = 0; u < 4; u++) {
                xA[u] = make_ulonglong2(0ull, 0ull);
                if (validA) xA[u] = xrA[(it0 + u) * 8 + c];
            }
            #pragma unroll
            for (int u = 0; u < 4; u++) {
                xB[u] = make_ulonglong2(0ull, 0ull);
                if (validB) xB[u] = xrB[(it0 + u) * 8 + c];
            }

            #pragma unroll
            for (int u = 0; u < 4; u++) {
                #pragma unroll
                for (int l = 0; l < LL; l++) {
                    ulonglong2 wv = Wp2[l * 256 + (it0 + u) * 8 + c];  // 128B bcast, no conflicts
                    asm("fma.rn.f32x2 %0, %1, %2, %0;" : "+l"(accA[l]) : "l"(xA[u].x), "l"(wv.x));
                    asm("fma.rn.f32x2 %0, %1, %2, %0;" : "+l"(accA[l]) : "l"(xA[u].y), "l"(wv.y));
                    asm("fma.rn.f32x2 %0, %1, %2, %0;" : "+l"(accB[l]) : "l"(xB[u].x), "l"(wv.x));
                    asm("fma.rn.f32x2 %0, %1, %2, %0;" : "+l"(accB[l]) : "l"(xB[u].y), "l"(wv.y));
                }
            }
        }
    }

    // unpack + reduce across the 8 K-slices (xor 1,2,4 within each rp group)
    float sumA[LL], sumB[LL];
    #pragma unroll
    for (int l = 0; l < LL; l++) {
        float lo, hi;
        asm("mov.b64 {%0, %1}, %2;" : "=f"(lo), "=f"(hi) : "l"(accA[l]));
        sumA[l] = lo + hi;
        asm("mov.b64 {%0, %1}, %2;" : "=f"(lo), "=f"(hi) : "l"(accB[l]));
        sumB[l] = lo + hi;
    }
    #pragma unroll
    for (int l = 0; l < LL; l++) {
        sumA[l] += __shfl_xor_sync(0xFFFFFFFFu, sumA[l], 1);
        sumA[l] += __shfl_xor_sync(0xFFFFFFFFu, sumA[l], 2);
        sumA[l] += __shfl_xor_sync(0xFFFFFFFFu, sumA[l], 4);
        sumB[l] += __shfl_xor_sync(0xFFFFFFFFu, sumB[l], 1);
        sumB[l] += __shfl_xor_sync(0xFFFFFFFFu, sumB[l], 2);
        sumB[l] += __shfl_xor_sync(0xFFFFFFFFu, sumB[l], 4);
    }

    if (c == 0) {
        float bi[LL];
        #pragma unroll
        for (int l = 0; l < LL; l++) bi[l] = bias[l];

        // ---- row A ----
        {
            float logit[LL];
            #pragma unroll
            for (int l = 0; l < LL; l++) logit[l] = validA ? (sumA[l] + bi[l]) : bi[l];
            float m = logit[0];
            #pragma unroll
            for (int l = 1; l < LL; l++) m = fmaxf(m, logit[l]);
            float e[LL], s = 0.f;
            #pragma unroll
            for (int l = 0; l < LL; l++) { e[l] = __expf(logit[l] - m); s += e[l]; }
            float inv = 1.0f / s;
            float* __restrict__ o = out + ((size_t)bA * SS + (size_t)j) * LL;
            #pragma unroll
            for (int l = 0; l < LL; l++) o[l] = e[l] * inv;
        }
        // ---- row B ----
        {
            float logit[LL];
            #pragma unroll
            for (int l = 0; l < LL; l++) logit[l] = validB ? (sumB[l] + bi[l]) : bi[l];
            float m = logit[0];
            #pragma unroll
            for (int l = 1; l < LL; l++) m = fmaxf(m, logit[l]);
            float e[LL], s = 0.f;
            #pragma unroll
            for (int l = 0; l < LL; l++) { e[l] = __expf(logit[l] - m); s += e[l]; }
            float inv = 1.0f / s;
            float* __restrict__ o = out + ((size_t)bB * SS + (size_t)j) * LL;
            #pragma unroll
            for (int l = 0; l < LL; l++) o[l] = e[l] * inv;
        }
    }
}

// ---------------------------------------------------------------------------
// Launch. Inputs: [0] seq f32 [64,512,1024], [1] mask i32 [64,512],
//                 [2] W f32 [1024,9], [3] b f32 [9]; out f32 [64,512,9]
// ---------------------------------------------------------------------------
extern "C" void kernel_launch(void* const* d_in, const int* in_sizes, int n_in,
                              void* d_out, int out_size)
{
    const float* seq  = (const float*)d_in[0];
    const int*   mask = (const int*)  d_in[1];
    const float* W    = (const float*)d_in[2];
    const float* bias = (const float*)d_in[3];
    float*       out  = (float*)d_out;

    ner_prep_kernel<<<BB, SS>>>(mask, W);
    ner_main_kernel<<<SS, MAIN_BLOCK>>>(seq, bias, out);   // one block per token slot
}